// round 3
// baseline (speedup 1.0000x reference)
#include <cuda_runtime.h>
#include <math.h>

#define NN 10000
#define EE 160000
#define CIN0 32
#define HH 64
#define TT 12
#define OUTC 12

typedef unsigned long long u64;

// ---------------- scratch (device globals; no allocation allowed) ----------------
__device__ float g_bufA[NN * 64 * 12];
__device__ float g_bufB[NN * 64 * 12];
__device__ int   g_cnt[NN];
__device__ int   g_fill[NN];
__device__ int   g_rowptr[NN + 1];
__device__ int   g_col[EE + NN];
__device__ float g_deg[NN];
__device__ float g_dis[NN];
__device__ float g_wc[EE + NN];
__device__ float2 g_wpk0[CIN0 * 3 * 64];
__device__ float2 g_wpk1[64 * 3 * 64];
__device__ float2 g_wpk2[64 * 3 * 64];
__device__ float2 g_wpk3[64 * 3 * 64];

// ---------------- f32x2 helpers ----------------
__device__ __forceinline__ u64 pk2(float a, float b) {
    u64 r; asm("mov.b64 %0, {%1, %2};" : "=l"(r) : "f"(a), "f"(b)); return r;
}
__device__ __forceinline__ void upk2(u64 v, float& a, float& b) {
    asm("mov.b64 {%0, %1}, %2;" : "=f"(a), "=f"(b) : "l"(v));
}
__device__ __forceinline__ u64 ffma2(u64 a, u64 b, u64 c) {
    u64 d; asm("fma.rn.f32x2 %0, %1, %2, %3;" : "=l"(d) : "l"(a), "l"(b), "l"(c)); return d;
}

// ---------------- CSR build ----------------
__global__ void csr_init(int* cnt, float* deg, int* fill) {
    int v = blockIdx.x * blockDim.x + threadIdx.x;
    if (v < NN) { cnt[v] = 1; deg[v] = 1.0f; fill[v] = 0; }
}

__global__ void csr_count(const int* __restrict__ dst, const float* __restrict__ ew,
                          int* cnt, float* deg) {
    int e = blockIdx.x * blockDim.x + threadIdx.x;
    if (e < EE) {
        int d = dst[e];
        atomicAdd(&cnt[d], 1);
        atomicAdd(&deg[d], ew[e]);
    }
}

__global__ void csr_dis(const float* __restrict__ deg, float* dis) {
    int v = blockIdx.x * blockDim.x + threadIdx.x;
    if (v < NN) dis[v] = rsqrtf(deg[v]);   // deg >= 1 always (self loop)
}

__global__ void scan_kernel(const int* __restrict__ cnt, int* __restrict__ rowptr) {
    __shared__ int part[1024];
    const int tid = threadIdx.x;
    const int CHUNK = 10;                  // 1024*10 = 10240 >= NN+1
    int base = tid * CHUNK;
    int local[CHUNK];
    int s = 0;
#pragma unroll
    for (int i = 0; i < CHUNK; i++) {
        int idx = base + i;
        int v = (idx < NN) ? cnt[idx] : 0;
        local[i] = s;
        s += v;
    }
    part[tid] = s;
    __syncthreads();
    for (int off = 1; off < 1024; off <<= 1) {
        int v = (tid >= off) ? part[tid - off] : 0;
        __syncthreads();
        part[tid] += v;
        __syncthreads();
    }
    int offset = (tid > 0) ? part[tid - 1] : 0;
#pragma unroll
    for (int i = 0; i < CHUNK; i++) {
        int idx = base + i;
        if (idx <= NN) rowptr[idx] = offset + local[i];
    }
}

__global__ void csr_fill(const int* __restrict__ src, const int* __restrict__ dst,
                         const float* __restrict__ ew, const float* __restrict__ dis,
                         const int* __restrict__ rowptr, int* fill,
                         int* __restrict__ col, float* __restrict__ wc) {
    int i = blockIdx.x * blockDim.x + threadIdx.x;
    if (i < EE) {
        int s = src[i], d = dst[i];
        int pos = rowptr[d] + atomicAdd(&fill[d], 1);
        col[pos] = s;
        wc[pos] = dis[s] * ew[i] * dis[d];
    } else if (i < EE + NN) {
        int v = i - EE;
        int pos = rowptr[v] + atomicAdd(&fill[v], 1);
        col[pos] = v;
        wc[pos] = dis[v] * dis[v];
    }
}

// ---------------- weight prepack for gated convs ----------------
// wpk[(ci*3+k)*64 + co] = { w[co][ci][k], w[co+64][ci][k] }
__global__ void prepack(const float* __restrict__ w, float2* __restrict__ wpk, int cin) {
    int i = blockIdx.x * blockDim.x + threadIdx.x;
    int total = cin * 3 * 64;
    if (i < total) {
        int co = i & 63;
        int ck = i >> 6;           // ci*3 + k
        int ci = ck / 3, k = ck - 3 * ci;
        wpk[i] = make_float2(w[co * cin * 3 + ci * 3 + k],
                             w[(co + 64) * cin * 3 + ci * 3 + k]);
    }
}

// ---------------- gated temporal conv (fused gating) ----------------
// block: (64, 4) = 64 co-pairs x 4 nodes. f32x2 accumulator = (P[co,t], Q[co,t]).
template <int CIN>
__global__ __launch_bounds__(256) void gated_conv(
        const float* __restrict__ hin,   // [N, CIN, 12]
        const float2* __restrict__ wpk,  // [(CIN*3)][64] paired
        const float* __restrict__ bias,  // [128]
        float* __restrict__ hout)        // [N, 64, 12]
{
    const int co = threadIdx.x;          // 0..63
    const int ln = threadIdx.y;          // 0..3
    const int node = blockIdx.x * 4 + ln;
    __shared__ float xs[4][CIN][16];     // xs[..][..][0]=pad, [1..12]=t, [13]=pad

    const float* xr = hin + (size_t)node * CIN * 12;
    for (int i = co; i < CIN * 12; i += 64) {
        int ci = i / 12, t = i - ci * 12;
        xs[ln][ci][t + 1] = xr[i];
    }
    for (int ci = co; ci < CIN; ci += 64) { xs[ln][ci][0] = 0.0f; xs[ln][ci][13] = 0.0f; }

    u64 acc[12];
    {
        u64 b0 = pk2(bias[co], bias[co + 64]);
#pragma unroll
        for (int t = 0; t < 12; t++) acc[t] = b0;
    }
    __syncthreads();

#pragma unroll 1
    for (int ci = 0; ci < CIN; ci++) {
        u64 xx[14];
#pragma unroll
        for (int j = 0; j < 14; j++) { float v = xs[ln][ci][j]; xx[j] = pk2(v, v); }
#pragma unroll
        for (int k = 0; k < 3; k++) {
            float2 w = __ldg(&wpk[(ci * 3 + k) * 64 + co]);
            u64 wp = pk2(w.x, w.y);
#pragma unroll
            for (int t = 0; t < 12; t++) acc[t] = ffma2(wp, xx[t + k], acc[t]);
        }
    }

    float ov[12];
#pragma unroll
    for (int t = 0; t < 12; t++) {
        float p, q; upk2(acc[t], p, q);
        ov[t] = p / (1.0f + expf(-q));       // P * sigmoid(Q)
    }
    float4* orow = (float4*)(hout + (size_t)node * 768 + co * 12);
#pragma unroll
    for (int j = 0; j < 3; j++)
        orow[j] = make_float4(ov[4 * j], ov[4 * j + 1], ov[4 * j + 2], ov[4 * j + 3]);
}

// ---------------- GCN aggregation: out[v] = sum_j w_j * hin[col_j] ----------------
__global__ __launch_bounds__(256) void agg_kernel(
        const float* __restrict__ hin, const int* __restrict__ rowptr,
        const int* __restrict__ col, const float* __restrict__ wc,
        float* __restrict__ out)
{
    const int v = blockIdx.x;
    const int tid = threadIdx.x;
    const int beg = rowptr[v], end = rowptr[v + 1];
    float a0 = 0.f, a1 = 0.f, a2 = 0.f;
    __shared__ int scol[64];
    __shared__ float sw[64];
    for (int j0 = beg; j0 < end; j0 += 64) {
        int m = min(64, end - j0);
        if (tid < m) { scol[tid] = col[j0 + tid] * 768; sw[tid] = wc[j0 + tid]; }
        __syncthreads();
#pragma unroll 4
        for (int i = 0; i < m; i++) {
            const float* p = hin + scol[i];
            float w = sw[i];
            a0 = fmaf(w, p[tid], a0);
            a1 = fmaf(w, p[tid + 256], a1);
            a2 = fmaf(w, p[tid + 512], a2);
        }
        __syncthreads();
    }
    float* o = out + (size_t)v * 768;
    o[tid] = a0; o[tid + 256] = a1; o[tid + 512] = a2;
}

// ---------------- GCN transform: out = relu(W @ agg + b) ----------------
// block (64, 4) = 64 o x 4 nodes; f32x2 over t-pairs.
__global__ __launch_bounds__(256) void gcn_transform(
        const float* __restrict__ agg, const float* __restrict__ W,
        const float* __restrict__ b, float* __restrict__ out)
{
    const int o = threadIdx.x;
    const int ln = threadIdx.y;
    const int node = blockIdx.x * 4 + ln;
    __shared__ u64 xs[4][64][6];
    __shared__ float Wsh[64][65];

    const float2* ar = (const float2*)(agg + (size_t)node * 768 + o * 12);
#pragma unroll
    for (int j = 0; j < 6; j++) { float2 v = ar[j]; xs[ln][o][j] = pk2(v.x, v.y); }
    for (int i = ln * 64 + o; i < 4096; i += 256) {
        int orow = i >> 6, c = i & 63;
        Wsh[c][orow] = W[i];
    }
    __syncthreads();

    u64 acc[6];
    {
        float bo = b[o];
        u64 b0 = pk2(bo, bo);
#pragma unroll
        for (int j = 0; j < 6; j++) acc[j] = b0;
    }
#pragma unroll 4
    for (int c = 0; c < 64; c++) {
        float w = Wsh[c][o];
        u64 wp = pk2(w, w);
#pragma unroll
        for (int j = 0; j < 6; j++) acc[j] = ffma2(wp, xs[ln][c][j], acc[j]);
    }

    float ov[12];
#pragma unroll
    for (int j = 0; j < 6; j++) {
        float p, q; upk2(acc[j], p, q);
        ov[2 * j]     = fmaxf(p, 0.0f);
        ov[2 * j + 1] = fmaxf(q, 0.0f);
    }
    float4* orow = (float4*)(out + (size_t)node * 768 + o * 12);
#pragma unroll
    for (int j = 0; j < 3; j++)
        orow[j] = make_float4(ov[4 * j], ov[4 * j + 1], ov[4 * j + 2], ov[4 * j + 3]);
}

// ---------------- final conv: out[n,o] = b[o] + sum_{c,t} fw[o,c,t]*h[n,c,t] ----------------
__global__ void final_conv(const float* __restrict__ h, const float* __restrict__ fw,
                           const float* __restrict__ fb, float* __restrict__ out)
{
    int i = blockIdx.x * blockDim.x + threadIdx.x;
    if (i >= NN * OUTC) return;
    int n = i / OUTC, o = i - n * OUTC;
    const float4* hr = (const float4*)(h + (size_t)n * 768);
    const float4* wr = (const float4*)(fw + o * 768);
    float acc = 0.f;
#pragma unroll 4
    for (int j = 0; j < 192; j++) {
        float4 a = hr[j], bv = wr[j];
        acc += a.x * bv.x + a.y * bv.y + a.z * bv.z + a.w * bv.w;
    }
    out[i] = acc + fb[o];
}

// ---------------- launch ----------------
extern "C" void kernel_launch(void* const* d_in, const int* in_sizes, int n_in,
                              void* d_out, int out_size) {
    const float* x      = (const float*)d_in[0];
    const int*   ei     = (const int*)d_in[1];
    const float* ew     = (const float*)d_in[2];
    const float* tc1a_w = (const float*)d_in[3];
    const float* tc1a_b = (const float*)d_in[4];
    const float* gc1_w  = (const float*)d_in[5];
    const float* gc1_b  = (const float*)d_in[6];
    const float* tc1b_w = (const float*)d_in[7];
    const float* tc1b_b = (const float*)d_in[8];
    const float* tc2a_w = (const float*)d_in[9];
    const float* tc2a_b = (const float*)d_in[10];
    const float* gc2_w  = (const float*)d_in[11];
    const float* gc2_b  = (const float*)d_in[12];
    const float* tc2b_w = (const float*)d_in[13];
    const float* tc2b_b = (const float*)d_in[14];
    const float* fin_w  = (const float*)d_in[15];
    const float* fin_b  = (const float*)d_in[16];

    const int* src = ei;
    const int* dst = ei + EE;

    float *bufA, *bufB, *deg, *dis, *wc;
    int *cnt, *fill, *rowptr, *col;
    float2 *wp0, *wp1, *wp2, *wp3;
    cudaGetSymbolAddress((void**)&bufA,   g_bufA);
    cudaGetSymbolAddress((void**)&bufB,   g_bufB);
    cudaGetSymbolAddress((void**)&deg,    g_deg);
    cudaGetSymbolAddress((void**)&dis,    g_dis);
    cudaGetSymbolAddress((void**)&wc,     g_wc);
    cudaGetSymbolAddress((void**)&cnt,    g_cnt);
    cudaGetSymbolAddress((void**)&fill,   g_fill);
    cudaGetSymbolAddress((void**)&rowptr, g_rowptr);
    cudaGetSymbolAddress((void**)&col,    g_col);
    cudaGetSymbolAddress((void**)&wp0,    g_wpk0);
    cudaGetSymbolAddress((void**)&wp1,    g_wpk1);
    cudaGetSymbolAddress((void**)&wp2,    g_wpk2);
    cudaGetSymbolAddress((void**)&wp3,    g_wpk3);

    // CSR build (shared by both GCN layers)
    csr_init<<<(NN + 255) / 256, 256>>>(cnt, deg, fill);
    csr_count<<<(EE + 255) / 256, 256>>>(dst, ew, cnt, deg);
    csr_dis<<<(NN + 255) / 256, 256>>>(deg, dis);
    scan_kernel<<<1, 1024>>>(cnt, rowptr);
    csr_fill<<<(EE + NN + 255) / 256, 256>>>(src, dst, ew, dis, rowptr, fill, col, wc);

    // weight prepack
    prepack<<<(CIN0 * 3 * 64 + 255) / 256, 256>>>(tc1a_w, wp0, CIN0);
    prepack<<<(64 * 3 * 64 + 255) / 256, 256>>>(tc1b_w, wp1, 64);
    prepack<<<(64 * 3 * 64 + 255) / 256, 256>>>(tc2a_w, wp2, 64);
    prepack<<<(64 * 3 * 64 + 255) / 256, 256>>>(tc2b_w, wp3, 64);

    dim3 cb(64, 4);
    // block 1
    gated_conv<CIN0><<<NN / 4, cb>>>(x, wp0, tc1a_b, bufA);
    agg_kernel<<<NN, 256>>>(bufA, rowptr, col, wc, bufB);
    gcn_transform<<<NN / 4, cb>>>(bufB, gc1_w, gc1_b, bufA);
    gated_conv<64><<<NN / 4, cb>>>(bufA, wp1, tc1b_b, bufB);
    // block 2
    gated_conv<64><<<NN / 4, cb>>>(bufB, wp2, tc2a_b, bufA);
    agg_kernel<<<NN, 256>>>(bufA, rowptr, col, wc, bufB);
    gcn_transform<<<NN / 4, cb>>>(bufB, gc2_w, gc2_b, bufA);
    gated_conv<64><<<NN / 4, cb>>>(bufA, wp3, tc2b_b, bufB);
    // head
    final_conv<<<(NN * OUTC + 255) / 256, 256>>>(bufB, fin_w, fin_b, (float*)d_out);
}

// round 4
// speedup vs baseline: 1.0235x; 1.0235x over previous
#include <cuda_runtime.h>
#include <math.h>

#define NN 10000
#define EE 160000
#define CIN0 32
#define HH 64
#define TT 12
#define OUTC 12

typedef unsigned long long u64;

// ---------------- scratch (device globals; no allocation allowed) ----------------
__device__ float g_bufA[NN * 64 * 12];
__device__ float g_bufB[NN * 64 * 12];
__device__ int   g_cnt[NN];
__device__ int   g_fill[NN];
__device__ int   g_rowptr[NN + 1];
__device__ int   g_col[EE + NN];
__device__ float g_deg[NN];
__device__ float g_dis[NN];
__device__ float g_wc[EE + NN];
__device__ float2 g_wpk0[CIN0 * 3 * 64];
__device__ float2 g_wpk1[64 * 3 * 64];
__device__ float2 g_wpk2[64 * 3 * 64];
__device__ float2 g_wpk3[64 * 3 * 64];

// ---------------- f32x2 helpers ----------------
__device__ __forceinline__ u64 pk2(float a, float b) {
    u64 r; asm("mov.b64 %0, {%1, %2};" : "=l"(r) : "f"(a), "f"(b)); return r;
}
__device__ __forceinline__ void upk2(u64 v, float& a, float& b) {
    asm("mov.b64 {%0, %1}, %2;" : "=f"(a), "=f"(b) : "l"(v));
}
__device__ __forceinline__ u64 ffma2(u64 a, u64 b, u64 c) {
    u64 d; asm("fma.rn.f32x2 %0, %1, %2, %3;" : "=l"(d) : "l"(a), "l"(b), "l"(c)); return d;
}

// ---------------- CSR build ----------------
__global__ void csr_init(int* cnt, float* deg, int* fill) {
    int v = blockIdx.x * blockDim.x + threadIdx.x;
    if (v < NN) { cnt[v] = 1; deg[v] = 1.0f; fill[v] = 0; }
}

__global__ void csr_count(const int* __restrict__ dst, const float* __restrict__ ew,
                          int* cnt, float* deg) {
    int e = blockIdx.x * blockDim.x + threadIdx.x;
    if (e < EE) {
        int d = dst[e];
        atomicAdd(&cnt[d], 1);
        atomicAdd(&deg[d], ew[e]);
    }
}

__global__ void csr_dis(const float* __restrict__ deg, float* dis) {
    int v = blockIdx.x * blockDim.x + threadIdx.x;
    if (v < NN) dis[v] = rsqrtf(deg[v]);   // deg >= 1 always (self loop)
}

__global__ void scan_kernel(const int* __restrict__ cnt, int* __restrict__ rowptr) {
    __shared__ int part[1024];
    const int tid = threadIdx.x;
    const int CHUNK = 10;                  // 1024*10 = 10240 >= NN+1
    int base = tid * CHUNK;
    int local[CHUNK];
    int s = 0;
#pragma unroll
    for (int i = 0; i < CHUNK; i++) {
        int idx = base + i;
        int v = (idx < NN) ? cnt[idx] : 0;
        local[i] = s;
        s += v;
    }
    part[tid] = s;
    __syncthreads();
    for (int off = 1; off < 1024; off <<= 1) {
        int v = (tid >= off) ? part[tid - off] : 0;
        __syncthreads();
        part[tid] += v;
        __syncthreads();
    }
    int offset = (tid > 0) ? part[tid - 1] : 0;
#pragma unroll
    for (int i = 0; i < CHUNK; i++) {
        int idx = base + i;
        if (idx <= NN) rowptr[idx] = offset + local[i];
    }
}

__global__ void csr_fill(const int* __restrict__ src, const int* __restrict__ dst,
                         const float* __restrict__ ew, const float* __restrict__ dis,
                         const int* __restrict__ rowptr, int* fill,
                         int* __restrict__ col, float* __restrict__ wc) {
    int i = blockIdx.x * blockDim.x + threadIdx.x;
    if (i < EE) {
        int s = src[i], d = dst[i];
        int pos = rowptr[d] + atomicAdd(&fill[d], 1);
        col[pos] = s;
        wc[pos] = dis[s] * ew[i] * dis[d];
    } else if (i < EE + NN) {
        int v = i - EE;
        int pos = rowptr[v] + atomicAdd(&fill[v], 1);
        col[pos] = v;
        wc[pos] = dis[v] * dis[v];
    }
}

// ---------------- weight prepack for gated convs ----------------
// wpk[(ci*3+k)*64 + co] = { w[co][ci][k], w[co+64][ci][k] }
__global__ void prepack(const float* __restrict__ w, float2* __restrict__ wpk, int cin) {
    int i = blockIdx.x * blockDim.x + threadIdx.x;
    int total = cin * 3 * 64;
    if (i < total) {
        int co = i & 63;
        int ck = i >> 6;           // ci*3 + k
        int ci = ck / 3, k = ck - 3 * ci;
        wpk[i] = make_float2(w[co * cin * 3 + ci * 3 + k],
                             w[(co + 64) * cin * 3 + ci * 3 + k]);
    }
}

// ---------------- gated temporal conv (fused gating) ----------------
// block: (64, 4) = 64 co-pairs x 4 nodes. f32x2 accumulator = (P[co,t], Q[co,t]).
template <int CIN>
__global__ __launch_bounds__(256) void gated_conv(
        const float* __restrict__ hin,   // [N, CIN, 12]
        const float2* __restrict__ wpk,  // [(CIN*3)][64] paired
        const float* __restrict__ bias,  // [128]
        float* __restrict__ hout)        // [N, 64, 12]
{
    const int co = threadIdx.x;          // 0..63
    const int ln = threadIdx.y;          // 0..3
    const int node = blockIdx.x * 4 + ln;
    __shared__ float xs[4][CIN][16];     // xs[..][..][0]=pad, [1..12]=t, [13]=pad

    const float* xr = hin + (size_t)node * CIN * 12;
    for (int i = co; i < CIN * 12; i += 64) {
        int ci = i / 12, t = i - ci * 12;
        xs[ln][ci][t + 1] = xr[i];
    }
    for (int ci = co; ci < CIN; ci += 64) { xs[ln][ci][0] = 0.0f; xs[ln][ci][13] = 0.0f; }

    u64 acc[12];
    {
        u64 b0 = pk2(bias[co], bias[co + 64]);
#pragma unroll
        for (int t = 0; t < 12; t++) acc[t] = b0;
    }
    __syncthreads();

#pragma unroll 1
    for (int ci = 0; ci < CIN; ci++) {
        u64 xx[14];
#pragma unroll
        for (int j = 0; j < 14; j++) { float v = xs[ln][ci][j]; xx[j] = pk2(v, v); }
#pragma unroll
        for (int k = 0; k < 3; k++) {
            float2 w = __ldg(&wpk[(ci * 3 + k) * 64 + co]);
            u64 wp = pk2(w.x, w.y);
#pragma unroll
            for (int t = 0; t < 12; t++) acc[t] = ffma2(wp, xx[t + k], acc[t]);
        }
    }

    float ov[12];
#pragma unroll
    for (int t = 0; t < 12; t++) {
        float p, q; upk2(acc[t], p, q);
        ov[t] = p / (1.0f + expf(-q));       // P * sigmoid(Q)
    }
    float4* orow = (float4*)(hout + (size_t)node * 768 + co * 12);
#pragma unroll
    for (int j = 0; j < 3; j++)
        orow[j] = make_float4(ov[4 * j], ov[4 * j + 1], ov[4 * j + 2], ov[4 * j + 3]);
}

// ---------------- GCN aggregation: out[v] = sum_j w_j * hin[col_j] ----------------
__global__ __launch_bounds__(256) void agg_kernel(
        const float* __restrict__ hin, const int* __restrict__ rowptr,
        const int* __restrict__ col, const float* __restrict__ wc,
        float* __restrict__ out)
{
    const int v = blockIdx.x;
    const int tid = threadIdx.x;
    const int beg = rowptr[v], end = rowptr[v + 1];
    float a0 = 0.f, a1 = 0.f, a2 = 0.f;
    __shared__ int scol[64];
    __shared__ float sw[64];
    for (int j0 = beg; j0 < end; j0 += 64) {
        int m = min(64, end - j0);
        if (tid < m) { scol[tid] = col[j0 + tid] * 768; sw[tid] = wc[j0 + tid]; }
        __syncthreads();
#pragma unroll 4
        for (int i = 0; i < m; i++) {
            const float* p = hin + scol[i];
            float w = sw[i];
            a0 = fmaf(w, p[tid], a0);
            a1 = fmaf(w, p[tid + 256], a1);
            a2 = fmaf(w, p[tid + 512], a2);
        }
        __syncthreads();
    }
    float* o = out + (size_t)v * 768;
    o[tid] = a0; o[tid + 256] = a1; o[tid + 512] = a2;
}

// ---------------- GCN transform: out = relu(W @ agg + b) ----------------
// block (64, 4) = 64 o x 4 nodes; f32x2 over t-pairs.
__global__ __launch_bounds__(256) void gcn_transform(
        const float* __restrict__ agg, const float* __restrict__ W,
        const float* __restrict__ b, float* __restrict__ out)
{
    const int o = threadIdx.x;
    const int ln = threadIdx.y;
    const int node = blockIdx.x * 4 + ln;
    __shared__ u64 xs[4][64][6];
    __shared__ float Wsh[64][65];

    const float2* ar = (const float2*)(agg + (size_t)node * 768 + o * 12);
#pragma unroll
    for (int j = 0; j < 6; j++) { float2 v = ar[j]; xs[ln][o][j] = pk2(v.x, v.y); }
    for (int i = ln * 64 + o; i < 4096; i += 256) {
        int orow = i >> 6, c = i & 63;
        Wsh[c][orow] = W[i];
    }
    __syncthreads();

    u64 acc[6];
    {
        float bo = b[o];
        u64 b0 = pk2(bo, bo);
#pragma unroll
        for (int j = 0; j < 6; j++) acc[j] = b0;
    }
#pragma unroll 4
    for (int c = 0; c < 64; c++) {
        float w = Wsh[c][o];
        u64 wp = pk2(w, w);
#pragma unroll
        for (int j = 0; j < 6; j++) acc[j] = ffma2(wp, xs[ln][c][j], acc[j]);
    }

    float ov[12];
#pragma unroll
    for (int j = 0; j < 6; j++) {
        float p, q; upk2(acc[j], p, q);
        ov[2 * j]     = fmaxf(p, 0.0f);
        ov[2 * j + 1] = fmaxf(q, 0.0f);
    }
    float4* orow = (float4*)(out + (size_t)node * 768 + o * 12);
#pragma unroll
    for (int j = 0; j < 3; j++)
        orow[j] = make_float4(ov[4 * j], ov[4 * j + 1], ov[4 * j + 2], ov[4 * j + 3]);
}

// ---------------- final conv: out[n,o] = b[o] + sum_{c,t} fw[o,c,t]*h[n,c,t] ----------------
__global__ void final_conv(const float* __restrict__ h, const float* __restrict__ fw,
                           const float* __restrict__ fb, float* __restrict__ out)
{
    int i = blockIdx.x * blockDim.x + threadIdx.x;
    if (i >= NN * OUTC) return;
    int n = i / OUTC, o = i - n * OUTC;
    const float4* hr = (const float4*)(h + (size_t)n * 768);
    const float4* wr = (const float4*)(fw + o * 768);
    float acc = 0.f;
#pragma unroll 4
    for (int j = 0; j < 192; j++) {
        float4 a = hr[j], bv = wr[j];
        acc += a.x * bv.x + a.y * bv.y + a.z * bv.z + a.w * bv.w;
    }
    out[i] = acc + fb[o];
}

// ---------------- launch ----------------
extern "C" void kernel_launch(void* const* d_in, const int* in_sizes, int n_in,
                              void* d_out, int out_size) {
    const float* x      = (const float*)d_in[0];
    const int*   ei     = (const int*)d_in[1];
    const float* ew     = (const float*)d_in[2];
    const float* tc1a_w = (const float*)d_in[3];
    const float* tc1a_b = (const float*)d_in[4];
    const float* gc1_w  = (const float*)d_in[5];
    const float* gc1_b  = (const float*)d_in[6];
    const float* tc1b_w = (const float*)d_in[7];
    const float* tc1b_b = (const float*)d_in[8];
    const float* tc2a_w = (const float*)d_in[9];
    const float* tc2a_b = (const float*)d_in[10];
    const float* gc2_w  = (const float*)d_in[11];
    const float* gc2_b  = (const float*)d_in[12];
    const float* tc2b_w = (const float*)d_in[13];
    const float* tc2b_b = (const float*)d_in[14];
    const float* fin_w  = (const float*)d_in[15];
    const float* fin_b  = (const float*)d_in[16];

    const int* src = ei;
    const int* dst = ei + EE;

    float *bufA, *bufB, *deg, *dis, *wc;
    int *cnt, *fill, *rowptr, *col;
    float2 *wp0, *wp1, *wp2, *wp3;
    cudaGetSymbolAddress((void**)&bufA,   g_bufA);
    cudaGetSymbolAddress((void**)&bufB,   g_bufB);
    cudaGetSymbolAddress((void**)&deg,    g_deg);
    cudaGetSymbolAddress((void**)&dis,    g_dis);
    cudaGetSymbolAddress((void**)&wc,     g_wc);
    cudaGetSymbolAddress((void**)&cnt,    g_cnt);
    cudaGetSymbolAddress((void**)&fill,   g_fill);
    cudaGetSymbolAddress((void**)&rowptr, g_rowptr);
    cudaGetSymbolAddress((void**)&col,    g_col);
    cudaGetSymbolAddress((void**)&wp0,    g_wpk0);
    cudaGetSymbolAddress((void**)&wp1,    g_wpk1);
    cudaGetSymbolAddress((void**)&wp2,    g_wpk2);
    cudaGetSymbolAddress((void**)&wp3,    g_wpk3);

    // CSR build (shared by both GCN layers)
    csr_init<<<(NN + 255) / 256, 256>>>(cnt, deg, fill);
    csr_count<<<(EE + 255) / 256, 256>>>(dst, ew, cnt, deg);
    csr_dis<<<(NN + 255) / 256, 256>>>(deg, dis);
    scan_kernel<<<1, 1024>>>(cnt, rowptr);
    csr_fill<<<(EE + NN + 255) / 256, 256>>>(src, dst, ew, dis, rowptr, fill, col, wc);

    // weight prepack
    prepack<<<(CIN0 * 3 * 64 + 255) / 256, 256>>>(tc1a_w, wp0, CIN0);
    prepack<<<(64 * 3 * 64 + 255) / 256, 256>>>(tc1b_w, wp1, 64);
    prepack<<<(64 * 3 * 64 + 255) / 256, 256>>>(tc2a_w, wp2, 64);
    prepack<<<(64 * 3 * 64 + 255) / 256, 256>>>(tc2b_w, wp3, 64);

    dim3 cb(64, 4);
    // block 1
    gated_conv<CIN0><<<NN / 4, cb>>>(x, wp0, tc1a_b, bufA);
    agg_kernel<<<NN, 256>>>(bufA, rowptr, col, wc, bufB);
    gcn_transform<<<NN / 4, cb>>>(bufB, gc1_w, gc1_b, bufA);
    gated_conv<64><<<NN / 4, cb>>>(bufA, wp1, tc1b_b, bufB);
    // block 2
    gated_conv<64><<<NN / 4, cb>>>(bufB, wp2, tc2a_b, bufA);
    agg_kernel<<<NN, 256>>>(bufA, rowptr, col, wc, bufB);
    gcn_transform<<<NN / 4, cb>>>(bufB, gc2_w, gc2_b, bufA);
    gated_conv<64><<<NN / 4, cb>>>(bufA, wp3, tc2b_b, bufB);
    // head
    final_conv<<<(NN * OUTC + 255) / 256, 256>>>(bufB, fin_w, fin_b, (float*)d_out);
}